// round 5
// baseline (speedup 1.0000x reference)
#include <cuda_runtime.h>
#include <cuda_bf16.h>
#include <cuda_fp16.h>
#include <cstdint>

#define BB 4
#define SS 4096
#define DD 512
#define BSD (BB*SS*DD)      // 8388608

// ---------------- device scratch (static; no allocations allowed) -------------
__device__ __nv_bfloat16 g_xhi[BSD];
__device__ __nv_bfloat16 g_xlo[BSD];
__device__ __nv_bfloat16 g_KQ[(size_t)BB*SS*2*DD];     // [16384, 1024] = K|Q
__device__ float         g_V[BSD];
__device__ __half        g_E[(size_t)BB*SS*SS];        // 128MB
__device__ float         g_cpart[(size_t)BB*32*SS];    // per-row-tile column partials
__device__ float         g_rc[BB*SS];   // 1/colsum
__device__ float         g_rs[BB*SS];   // rowsum
__device__ __nv_bfloat16 g_Wkq[2*DD*DD];
__device__ float         g_bkq[2*DD];
__device__ __nv_bfloat16 g_Wvhi[DD*DD], g_Wvlo[DD*DD];
__device__ __nv_bfloat16 g_Wlhi[DD*DD], g_Wllo[DD*DD];

// ---------------- helpers ----------------------------------------------------
__device__ __forceinline__ unsigned sptr(const void* p){
    return (unsigned)__cvta_generic_to_shared(p);
}
__device__ __forceinline__ void ldm4(unsigned r[4], unsigned addr){
    asm volatile("ldmatrix.sync.aligned.m8n8.x4.shared.b16 {%0,%1,%2,%3}, [%4];"
        : "=r"(r[0]),"=r"(r[1]),"=r"(r[2]),"=r"(r[3]) : "r"(addr));
}
__device__ __forceinline__ void mma16816(float c[4], const unsigned a[4], const unsigned b[2]){
    asm volatile("mma.sync.aligned.m16n8k16.row.col.f32.bf16.bf16.f32 "
        "{%0,%1,%2,%3},{%4,%5,%6,%7},{%8,%9},{%0,%1,%2,%3};"
        : "+f"(c[0]),"+f"(c[1]),"+f"(c[2]),"+f"(c[3])
        : "r"(a[0]),"r"(a[1]),"r"(a[2]),"r"(a[3]),"r"(b[0]),"r"(b[1]));
}

// ---------------- prep --------------------------------------------------------
__global__ void prep_kernel(const float* __restrict__ xs, const float* __restrict__ Wk,
                            const float* __restrict__ Wq, const float* __restrict__ Wv,
                            const float* __restrict__ Wl, const float* __restrict__ bk,
                            const float* __restrict__ bq){
    long i = (long)blockIdx.x*blockDim.x + threadIdx.x;
    if (i < (long)BSD){
        float v = xs[i];
        __nv_bfloat16 h = __float2bfloat16(v);
        g_xhi[i] = h;
        g_xlo[i] = __float2bfloat16(v - __bfloat162float(h));
    }
    if (i < DD*DD){
        g_Wkq[i]         = __float2bfloat16(Wk[i]);
        g_Wkq[DD*DD + i] = __float2bfloat16(Wq[i]);
        float wv = Wv[i]; __nv_bfloat16 vh = __float2bfloat16(wv);
        g_Wvhi[i] = vh; g_Wvlo[i] = __float2bfloat16(wv - __bfloat162float(vh));
        float wl = Wl[i]; __nv_bfloat16 lh = __float2bfloat16(wl);
        g_Wlhi[i] = lh; g_Wllo[i] = __float2bfloat16(wl - __bfloat162float(lh));
    }
    if (i < DD){
        g_bkq[i] = bk[i]; g_bkq[DD + i] = bq[i];
    }
}

// ======================= QK kernel: HMMA, 64x64 warp tiles ====================
// 128 threads, 4 warps in 2x2 grid, block tile 128x128, K-chunk 32.
// E = exp(K Q^T / 512) -> fp16, plus fused fp16-rounded column partial sums.
constexpr int LDSQ = 40;

__global__ void __launch_bounds__(128) qk_kernel(){
    __shared__ __nv_bfloat16 sm[2*128*LDSQ];   // As | Bs (20480 B)
    __nv_bfloat16* As = sm;
    __nv_bfloat16* Bs = sm + 128*LDSQ;

    int tid = threadIdx.x, lane = tid & 31, warp = tid >> 5;
    int wm = warp >> 1, wn = warp & 1;         // 2x2 -> 64x64 per warp
    int z = blockIdx.z, by = blockIdx.y, bx = blockIdx.x;
    int bm0 = by*128, bn0 = bx*128;

    const __nv_bfloat16* Krow = g_KQ + ((long)(z*SS + bm0 + tid))*(2*DD);
    const __nv_bfloat16* Qrow = g_KQ + ((long)(z*SS + bn0 + tid))*(2*DD) + DD;

    float acc[4][8][4] = {};

    for (int k0 = 0; k0 < DD; k0 += 32){
        // each thread loads one 64B row-chunk of A and of B
        {
            const uint4* a = (const uint4*)(Krow + k0);
            const uint4* b = (const uint4*)(Qrow + k0);
            uint4* da = (uint4*)(As + tid*LDSQ);
            uint4* db = (uint4*)(Bs + tid*LDSQ);
            da[0]=a[0]; da[1]=a[1]; da[2]=a[2]; da[3]=a[3];
            db[0]=b[0]; db[1]=b[1]; db[2]=b[2]; db[3]=b[3];
        }
        __syncthreads();

        #pragma unroll
        for (int kk = 0; kk < 32; kk += 16){
            unsigned af[4][4], bf[8][2];
            int arow = wm*64 + (lane & 15);
            int acol = kk + 8*(lane >> 4);
            #pragma unroll
            for (int mi=0; mi<4; mi++)
                ldm4(af[mi], sptr(As + (arow + mi*16)*LDSQ + acol));
            int brow = wn*64 + (lane & 7) + ((lane & 16) ? 8 : 0);
            int bcol = kk + ((lane & 8) ? 8 : 0);
            #pragma unroll
            for (int nb=0; nb<4; nb++){
                unsigned tmp[4];
                ldm4(tmp, sptr(Bs + (brow + nb*16)*LDSQ + bcol));
                bf[2*nb][0]=tmp[0]; bf[2*nb][1]=tmp[1];
                bf[2*nb+1][0]=tmp[2]; bf[2*nb+1][1]=tmp[3];
            }
            #pragma unroll
            for (int mi=0; mi<4; mi++)
                #pragma unroll
                for (int ni=0; ni<8; ni++)
                    mma16816(acc[mi][ni], af[mi], bf[ni]);
        }
        __syncthreads();
    }

    // ---------- epilogue: exp -> fp16 E store + fused column partials ----------
    const float inv = 1.0f/512.0f;
    int tr = lane >> 2, tc = (lane & 3) * 2;
    __half* C = g_E + (long)z*SS*SS;
    float csum[8][2];
    #pragma unroll
    for (int ni=0; ni<8; ni++){ csum[ni][0]=0.f; csum[ni][1]=0.f; }

    #pragma unroll
    for (int mi=0; mi<4; mi++){
        #pragma unroll
        for (int ni=0; ni<8; ni++){
            int row = bm0 + wm*64 + mi*16 + tr;
            int col = bn0 + wn*64 + ni*8 + tc;
            float* a = acc[mi][ni];
            // round to fp16 FIRST; sum the rounded value (error cancels in ratio)
            __half h0 = __float2half_rn(__expf(a[0]*inv));
            __half h1 = __float2half_rn(__expf(a[1]*inv));
            __half h2 = __float2half_rn(__expf(a[2]*inv));
            __half h3 = __float2half_rn(__expf(a[3]*inv));
            *(__half2*)(C + (long)row*SS + col)     = __halves2half2(h0, h1);
            *(__half2*)(C + (long)(row+8)*SS + col) = __halves2half2(h2, h3);
            csum[ni][0] += __half2float(h0) + __half2float(h2);
            csum[ni][1] += __half2float(h1) + __half2float(h3);
        }
    }
    #pragma unroll
    for (int ni=0; ni<8; ni++)
        #pragma unroll
        for (int j=0; j<2; j++){
            float s = csum[ni][j];
            s += __shfl_xor_sync(0xffffffffu, s, 4);
            s += __shfl_xor_sync(0xffffffffu, s, 8);
            s += __shfl_xor_sync(0xffffffffu, s, 16);
            csum[ni][j] = s;
        }
    float* cps = (float*)sm;   // smem reuse: mainloop done (trailing syncthreads)
    if (lane < 4){
        #pragma unroll
        for (int ni=0; ni<8; ni++){
            cps[wm*128 + wn*64 + ni*8 + tc]     = csum[ni][0];
            cps[wm*128 + wn*64 + ni*8 + tc + 1] = csum[ni][1];
        }
    }
    __syncthreads();
    g_cpart[((long)z*32 + by)*SS + bn0 + tid] = cps[tid] + cps[128 + tid];
}

// ---------------- HMMA GEMM (round-3 proven) for projections + output ---------
// EPI: 0 bf16+bias | 1 fp32+bias | 3 tanh+bias fp32
constexpr int Bb_M = 128, Bb_N = 128, Bb_K = 32, LDS = 40;

template<int EPI, bool SPLIT, bool AFV>
__global__ void __launch_bounds__(256)
gemm_kernel(const __nv_bfloat16* __restrict__ A, const __nv_bfloat16* __restrict__ A2,
            const __nv_bfloat16* __restrict__ B, const __nv_bfloat16* __restrict__ B2,
            const float* __restrict__ bias, void* __restrict__ Cout,
            int Kd, int lda, int ldb, int ldc,
            const float* __restrict__ rsG)
{
    extern __shared__ __nv_bfloat16 smx[];
    constexpr int AR = Bb_M*LDS;
    __nv_bfloat16* As  = smx;
    __nv_bfloat16* Bs  = smx + AR;
    __nv_bfloat16* As2 = SPLIT ? smx + 2*AR : nullptr;
    __nv_bfloat16* Bs2 = SPLIT ? smx + 3*AR : nullptr;

    const __nv_bfloat16* Ag  = A;
    const __nv_bfloat16* Bg  = B;
    const __nv_bfloat16* A2g = (SPLIT && !AFV) ? A2 : nullptr;
    const __nv_bfloat16* B2g = SPLIT ? B2 : nullptr;

    int tid = threadIdx.x, lane = tid & 31, warp = tid >> 5;
    int wm = warp >> 2, wn = warp & 3;
    int bm0 = blockIdx.y * Bb_M, bn0 = blockIdx.x * Bb_N;
    int lr = tid >> 1;
    int lc = (tid & 1) * 8;

    const float* Vg = nullptr; float rsv = 0.f;
    if (AFV){ Vg = (const float*)A; rsv = rsG[bm0 + lr]; }

    float acc[4][4][4] = {};

    for (int k0 = 0; k0 < Kd; k0 += Bb_K){
        if (!AFV){
            const __nv_bfloat16* a = Ag + (long)(bm0+lr)*lda + k0 + lc;
            *(uint4*)(As + lr*LDS + lc)      = *(const uint4*)(a);
            *(uint4*)(As + lr*LDS + lc + 16) = *(const uint4*)(a + 16);
            if (SPLIT){
                const __nv_bfloat16* a2 = A2g + (long)(bm0+lr)*lda + k0 + lc;
                *(uint4*)(As2 + lr*LDS + lc)      = *(const uint4*)(a2);
                *(uint4*)(As2 + lr*LDS + lc + 16) = *(const uint4*)(a2 + 16);
            }
        } else {
            int fo = (tid & 1) * 16;
            const float* v = Vg + (long)(bm0+lr)*lda + k0 + fo;
            #pragma unroll
            for (int q = 0; q < 4; q++){
                float4 fv = *(const float4*)(v + 4*q);
                float a0 = rsv*fv.x, a1 = rsv*fv.y, a2v = rsv*fv.z, a3 = rsv*fv.w;
                __nv_bfloat16 h0=__float2bfloat16(a0), h1=__float2bfloat16(a1),
                              h2=__float2bfloat16(a2v), h3=__float2bfloat16(a3);
                __nv_bfloat162 hp0; hp0.x=h0; hp0.y=h1;
                __nv_bfloat162 hp1; hp1.x=h2; hp1.y=h3;
                *(__nv_bfloat162*)(As + lr*LDS + fo + 4*q)     = hp0;
                *(__nv_bfloat162*)(As + lr*LDS + fo + 4*q + 2) = hp1;
                __nv_bfloat162 lp0, lp1;
                lp0.x = __float2bfloat16(a0  - __bfloat162float(h0));
                lp0.y = __float2bfloat16(a1  - __bfloat162float(h1));
                lp1.x = __float2bfloat16(a2v - __bfloat162float(h2));
                lp1.y = __float2bfloat16(a3  - __bfloat162float(h3));
                *(__nv_bfloat162*)(As2 + lr*LDS + fo + 4*q)     = lp0;
                *(__nv_bfloat162*)(As2 + lr*LDS + fo + 4*q + 2) = lp1;
            }
        }
        {
            const __nv_bfloat16* b = Bg + (long)(bn0+lr)*ldb + k0 + lc;
            *(uint4*)(Bs + lr*LDS + lc)      = *(const uint4*)(b);
            *(uint4*)(Bs + lr*LDS + lc + 16) = *(const uint4*)(b + 16);
            if (SPLIT){
                const __nv_bfloat16* b2 = B2g + (long)(bn0+lr)*ldb + k0 + lc;
                *(uint4*)(Bs2 + lr*LDS + lc)      = *(const uint4*)(b2);
                *(uint4*)(Bs2 + lr*LDS + lc + 16) = *(const uint4*)(b2 + 16);
            }
        }
        __syncthreads();

        #pragma unroll
        for (int kk = 0; kk < Bb_K; kk += 16){
            unsigned af[4][4], bf[4][2];
            unsigned af2[4][4], bf2[4][2];
            int arow = wm*64 + (lane & 15);
            int acol = kk + 8*(lane >> 4);
            #pragma unroll
            for (int mi=0; mi<4; mi++){
                ldm4(af[mi],  sptr(As  + (arow + mi*16)*LDS + acol));
                if (SPLIT) ldm4(af2[mi], sptr(As2 + (arow + mi*16)*LDS + acol));
            }
            int brow = wn*32 + (lane & 7) + ((lane & 16) ? 8 : 0);
            int bcol = kk + ((lane & 8) ? 8 : 0);
            #pragma unroll
            for (int nb=0; nb<2; nb++){
                unsigned tmp[4];
                ldm4(tmp, sptr(Bs + (brow + nb*16)*LDS + bcol));
                bf[2*nb][0]=tmp[0]; bf[2*nb][1]=tmp[1];
                bf[2*nb+1][0]=tmp[2]; bf[2*nb+1][1]=tmp[3];
                if (SPLIT){
                    ldm4(tmp, sptr(Bs2 + (brow + nb*16)*LDS + bcol));
                    bf2[2*nb][0]=tmp[0]; bf2[2*nb][1]=tmp[1];
                    bf2[2*nb+1][0]=tmp[2]; bf2[2*nb+1][1]=tmp[3];
                }
            }
            #pragma unroll
            for (int mi=0; mi<4; mi++)
                #pragma unroll
                for (int ni=0; ni<4; ni++){
                    mma16816(acc[mi][ni], af[mi], bf[ni]);
                    if (SPLIT){
                        mma16816(acc[mi][ni], af[mi],  bf2[ni]);
                        mma16816(acc[mi][ni], af2[mi], bf[ni]);
                    }
                }
        }
        __syncthreads();
    }

    int tr = lane >> 2, tc = (lane & 3) * 2;
    #pragma unroll
    for (int mi=0; mi<4; mi++){
        #pragma unroll
        for (int ni=0; ni<4; ni++){
            int row = bm0 + wm*64 + mi*16 + tr;
            int col = bn0 + wn*32 + ni*8 + tc;
            float* a = acc[mi][ni];
            if (EPI == 0){
                __nv_bfloat16* C = (__nv_bfloat16*)Cout;
                float b0 = bias[col], b1 = bias[col+1];
                *(__nv_bfloat162*)(C + (long)row*ldc + col)     = __floats2bfloat162_rn(a[0]+b0, a[1]+b1);
                *(__nv_bfloat162*)(C + (long)(row+8)*ldc + col) = __floats2bfloat162_rn(a[2]+b0, a[3]+b1);
            } else if (EPI == 1){
                float* C = (float*)Cout;
                float b0 = bias[col], b1 = bias[col+1];
                *(float2*)(C + (long)row*ldc + col)     = make_float2(a[0]+b0, a[1]+b1);
                *(float2*)(C + (long)(row+8)*ldc + col) = make_float2(a[2]+b0, a[3]+b1);
            } else {
                float* C = (float*)Cout;
                float b0 = bias[col], b1 = bias[col+1];
                *(float2*)(C + (long)row*ldc + col)     = make_float2(tanhf(a[0]+b0), tanhf(a[1]+b1));
                *(float2*)(C + (long)(row+8)*ldc + col) = make_float2(tanhf(a[2]+b0), tanhf(a[3]+b1));
            }
        }
    }
}

// ---------------- rc[b,e] = 1 / sum of column partials ------------------------
__global__ void __launch_bounds__(256) rc_kernel(){
    int i = blockIdx.x*256 + threadIdx.x;       // 0..16383
    int b = i >> 12, e = i & (SS-1);
    const float* p = g_cpart + (long)b*32*SS + e;
    float s = 0.f;
    #pragma unroll
    for (int t = 0; t < 32; t++) s += p[(long)t*SS];
    g_rc[i] = 1.0f/s;
}

// ---------------- rowsum: rs[b,s] = sum_e E[b,s,e] * rc[b,e] ------------------
__global__ void __launch_bounds__(256) rowsum_kernel(){
    __shared__ float rcs[SS];
    int b = blockIdx.y;
    for (int i = threadIdx.x; i < SS; i += 256) rcs[i] = g_rc[b*SS + i];
    __syncthreads();
    int lane = threadIdx.x & 31, warp = threadIdx.x >> 5;
    int r0 = blockIdx.x*64 + warp*8;
    for (int k = 0; k < 8; k++){
        int r = r0 + k;
        const __half2* row = (const __half2*)(g_E + ((long)b*SS + r)*(long)SS);
        float s = 0.f;
        for (int j = lane; j < SS/2; j += 32){
            float2 f = __half22float2(row[j]);
            s += f.x*rcs[2*j] + f.y*rcs[2*j+1];
        }
        #pragma unroll
        for (int o = 16; o; o >>= 1) s += __shfl_xor_sync(0xffffffffu, s, o);
        if (lane == 0) g_rs[b*SS + r] = s;
    }
}

// ---------------- launch -----------------------------------------------------
extern "C" void kernel_launch(void* const* d_in, const int* in_sizes, int n_in,
                              void* d_out, int out_size)
{
    const float* xs = (const float*)d_in[0];
    const float* Wk = (const float*)d_in[1]; const float* bk = (const float*)d_in[2];
    const float* Wq = (const float*)d_in[3]; const float* bq = (const float*)d_in[4];
    const float* Wv = (const float*)d_in[5]; const float* bv = (const float*)d_in[6];
    const float* Wl = (const float*)d_in[7]; const float* bl = (const float*)d_in[8];

    void *p_xhi,*p_xlo,*p_V,*p_bkq,*p_Wkq;
    void *p_Wvhi,*p_Wvlo,*p_Wlhi,*p_Wllo,*p_rs,*p_KQ;
    cudaGetSymbolAddress(&p_xhi, g_xhi);   cudaGetSymbolAddress(&p_xlo, g_xlo);
    cudaGetSymbolAddress(&p_KQ,  g_KQ);    cudaGetSymbolAddress(&p_V,   g_V);
    cudaGetSymbolAddress(&p_bkq, g_bkq);   cudaGetSymbolAddress(&p_Wkq, g_Wkq);
    cudaGetSymbolAddress(&p_Wvhi,g_Wvhi);  cudaGetSymbolAddress(&p_Wvlo,g_Wvlo);
    cudaGetSymbolAddress(&p_Wlhi,g_Wlhi);  cudaGetSymbolAddress(&p_Wllo,g_Wllo);
    cudaGetSymbolAddress(&p_rs,  g_rs);

    constexpr int AR = Bb_M*LDS;
    const size_t smemPlain = (size_t)2*AR*sizeof(__nv_bfloat16);   // 20480
    const size_t smemSplit = (size_t)4*AR*sizeof(__nv_bfloat16);   // 40960

    // 1. prep
    prep_kernel<<<(BSD + 255)/256, 256>>>(xs, Wk, Wq, Wv, Wl, bk, bq);

    // 2. merged K|Q projection -> g_KQ [16384, 1024]
    dim3 gkq(2*DD/Bb_N, (BB*SS)/Bb_M, 1);   // (8, 128)
    gemm_kernel<0,false,false><<<gkq, 256, smemPlain>>>(
        (const __nv_bfloat16*)p_xhi, nullptr, (const __nv_bfloat16*)p_Wkq, nullptr,
        (const float*)p_bkq, p_KQ, DD, DD, DD, 2*DD, nullptr);

    // 3. V projection (split, fp32 out)
    dim3 gp(DD/Bb_N, (BB*SS)/Bb_M, 1);      // (4, 128)
    gemm_kernel<1,true,false><<<gp, 256, smemSplit>>>(
        (const __nv_bfloat16*)p_xhi, (const __nv_bfloat16*)p_xlo,
        (const __nv_bfloat16*)p_Wvhi, (const __nv_bfloat16*)p_Wvlo,
        bv, p_V, DD, DD, DD, DD, nullptr);

    // 4. E = exp(K Q^T / 512) fp16 + fused column partials (64x64-tile HMMA)
    qk_kernel<<<dim3(SS/128, SS/128, BB), 128>>>();

    // 5. rc; 6. rowsum
    rc_kernel<<<BB*SS/256, 256>>>();
    rowsum_kernel<<<dim3(SS/64, BB), 256>>>();

    // 7. out = tanh((rs*V) Wl^T + bl)
    gemm_kernel<3,true,true><<<gp, 256, smemSplit>>>(
        (const __nv_bfloat16*)p_V, nullptr,
        (const __nv_bfloat16*)p_Wlhi, (const __nv_bfloat16*)p_Wllo,
        bl, d_out, DD, DD, DD, DD, (const float*)p_rs);
}

// round 6
// speedup vs baseline: 1.0887x; 1.0887x over previous
#include <cuda_runtime.h>
#include <cuda_bf16.h>
#include <cuda_fp16.h>
#include <cstdint>

#define BB 4
#define SS 4096
#define DD 512
#define BSD (BB*SS*DD)      // 8388608

// ---------------- device scratch (static; no allocations allowed) -------------
__device__ __nv_bfloat16 g_xhi[BSD];
__device__ __nv_bfloat16 g_xlo[BSD];
__device__ __nv_bfloat16 g_KQ[(size_t)BB*SS*2*DD];     // [16384, 1024] = K|Q
__device__ __half        g_E[(size_t)BB*SS*SS];        // 128MB
__device__ float         g_cpart[(size_t)BB*32*SS];    // per-row-tile column partials
__device__ float         g_rc[BB*SS];   // 1/colsum
__device__ float         g_rs[BB*SS];   // rowsum
__device__ __nv_bfloat16 g_Wkq[2*DD*DD];
__device__ float         g_bkq[2*DD];
__device__ __nv_bfloat16 g_Mhi[DD*DD], g_Mlo[DD*DD];   // M = Wl @ Wv, hi/lo split
__device__ float         g_c[DD];                      // c = Wl @ bv

// ---------------- helpers ----------------------------------------------------
__device__ __forceinline__ unsigned sptr(const void* p){
    return (unsigned)__cvta_generic_to_shared(p);
}
__device__ __forceinline__ void ldm4(unsigned r[4], unsigned addr){
    asm volatile("ldmatrix.sync.aligned.m8n8.x4.shared.b16 {%0,%1,%2,%3}, [%4];"
        : "=r"(r[0]),"=r"(r[1]),"=r"(r[2]),"=r"(r[3]) : "r"(addr));
}
__device__ __forceinline__ void mma16816(float c[4], const unsigned a[4], const unsigned b[2]){
    asm volatile("mma.sync.aligned.m16n8k16.row.col.f32.bf16.bf16.f32 "
        "{%0,%1,%2,%3},{%4,%5,%6,%7},{%8,%9},{%0,%1,%2,%3};"
        : "+f"(c[0]),"+f"(c[1]),"+f"(c[2]),"+f"(c[3])
        : "r"(a[0]),"r"(a[1]),"r"(a[2]),"r"(a[3]),"r"(b[0]),"r"(b[1]));
}

// ---------------- prep: x hi/lo split + KQ weight stack -----------------------
__global__ void prep_kernel(const float* __restrict__ xs, const float* __restrict__ Wk,
                            const float* __restrict__ Wq, const float* __restrict__ bk,
                            const float* __restrict__ bq){
    long i = (long)blockIdx.x*blockDim.x + threadIdx.x;
    if (i < (long)BSD){
        float v = xs[i];
        __nv_bfloat16 h = __float2bfloat16(v);
        g_xhi[i] = h;
        g_xlo[i] = __float2bfloat16(v - __bfloat162float(h));
    }
    if (i < DD*DD){
        g_Wkq[i]         = __float2bfloat16(Wk[i]);
        g_Wkq[DD*DD + i] = __float2bfloat16(Wq[i]);
    }
    if (i < DD){
        g_bkq[i] = bk[i]; g_bkq[DD + i] = bq[i];
    }
}

// ---------------- M = Wl @ Wv (fp32 tiled) -> hi/lo bf16 split ----------------
__global__ void matM_kernel(const float* __restrict__ Wl, const float* __restrict__ Wv){
    __shared__ float sA[16][16], sB[16][17];
    int tx = threadIdx.x, ty = threadIdx.y;
    int e = blockIdx.y*16 + ty, d = blockIdx.x*16 + tx;
    float acc = 0.f;
    for (int t0 = 0; t0 < DD; t0 += 16){
        sA[ty][tx] = Wl[e*DD + t0 + tx];
        sB[ty][tx] = Wv[(t0 + ty)*DD + d];
        __syncthreads();
        #pragma unroll
        for (int t = 0; t < 16; t++) acc += sA[ty][t]*sB[t][tx];
        __syncthreads();
    }
    __nv_bfloat16 h = __float2bfloat16(acc);
    g_Mhi[e*DD + d] = h;
    g_Mlo[e*DD + d] = __float2bfloat16(acc - __bfloat162float(h));
}

// ---------------- c = Wl @ bv (one warp per output) ---------------------------
__global__ void cvec_kernel(const float* __restrict__ Wl, const float* __restrict__ bv){
    int e = blockIdx.x*8 + (threadIdx.x >> 5), lane = threadIdx.x & 31;
    float s = 0.f;
    for (int d = lane; d < DD; d += 32) s += Wl[e*DD + d]*bv[d];
    #pragma unroll
    for (int o = 16; o; o >>= 1) s += __shfl_xor_sync(0xffffffffu, s, o);
    if (lane == 0) g_c[e] = s;
}

// ---------------- generic C = A * B^T GEMM (round-3 proven mainloop) ----------
// EPI: 0 bf16+bias (K|Q proj)
//      2 exp->fp16 E + fp16-rounded column partials (QK)
//      4 tanh(rs*(acc + c) + bias) -> fp32 (final fused output)
// SPLIT: 3-product hi/lo accumulation.
constexpr int Bb_M = 128, Bb_N = 128, Bb_K = 32, LDS = 40;

template<int EPI, bool SPLIT>
__global__ void __launch_bounds__(256)
gemm_kernel(const __nv_bfloat16* __restrict__ A, const __nv_bfloat16* __restrict__ A2,
            const __nv_bfloat16* __restrict__ B, const __nv_bfloat16* __restrict__ B2,
            const float* __restrict__ bias, void* __restrict__ Cout,
            int Kd, int lda, int ldb, int ldc,
            long batchA, long batchB, long batchC,
            const float* __restrict__ rsG, const float* __restrict__ cG)
{
    extern __shared__ __nv_bfloat16 sm[];
    constexpr int AR = Bb_M*LDS;
    __nv_bfloat16* As  = sm;
    __nv_bfloat16* Bs  = sm + AR;
    __nv_bfloat16* As2 = SPLIT ? sm + 2*AR : nullptr;
    __nv_bfloat16* Bs2 = SPLIT ? sm + 3*AR : nullptr;

    int z = blockIdx.z;
    const __nv_bfloat16* Ag  = A + z*batchA;
    const __nv_bfloat16* Bg  = B + z*batchB;
    const __nv_bfloat16* A2g = SPLIT ? A2 + z*batchA : nullptr;
    const __nv_bfloat16* B2g = SPLIT ? B2 + z*batchB : nullptr;

    int tid = threadIdx.x, lane = tid & 31, warp = tid >> 5;
    int wm = warp >> 2, wn = warp & 3;           // 2x4 warp grid -> 64x32 per warp
    int bm0 = blockIdx.y * Bb_M, bn0 = blockIdx.x * Bb_N;
    int lr = tid >> 1;                            // loader row 0..127
    int lc = (tid & 1) * 8;                       // loader col (halfs)

    float acc[4][4][4] = {};

    for (int k0 = 0; k0 < Kd; k0 += Bb_K){
        {
            const __nv_bfloat16* a = Ag + (long)(bm0+lr)*lda + k0 + lc;
            *(uint4*)(As + lr*LDS + lc)      = *(const uint4*)(a);
            *(uint4*)(As + lr*LDS + lc + 16) = *(const uint4*)(a + 16);
            if (SPLIT){
                const __nv_bfloat16* a2 = A2g + (long)(bm0+lr)*lda + k0 + lc;
                *(uint4*)(As2 + lr*LDS + lc)      = *(const uint4*)(a2);
                *(uint4*)(As2 + lr*LDS + lc + 16) = *(const uint4*)(a2 + 16);
            }
            const __nv_bfloat16* b = Bg + (long)(bn0+lr)*ldb + k0 + lc;
            *(uint4*)(Bs + lr*LDS + lc)      = *(const uint4*)(b);
            *(uint4*)(Bs + lr*LDS + lc + 16) = *(const uint4*)(b + 16);
            if (SPLIT){
                const __nv_bfloat16* b2 = B2g + (long)(bn0+lr)*ldb + k0 + lc;
                *(uint4*)(Bs2 + lr*LDS + lc)      = *(const uint4*)(b2);
                *(uint4*)(Bs2 + lr*LDS + lc + 16) = *(const uint4*)(b2 + 16);
            }
        }
        __syncthreads();

        #pragma unroll
        for (int kk = 0; kk < Bb_K; kk += 16){
            unsigned af[4][4], bf[4][2];
            unsigned af2[4][4], bf2[4][2];
            int arow = wm*64 + (lane & 15);
            int acol = kk + 8*(lane >> 4);
            #pragma unroll
            for (int mi=0; mi<4; mi++){
                ldm4(af[mi],  sptr(As  + (arow + mi*16)*LDS + acol));
                if (SPLIT) ldm4(af2[mi], sptr(As2 + (arow + mi*16)*LDS + acol));
            }
            int brow = wn*32 + (lane & 7) + ((lane & 16) ? 8 : 0);
            int bcol = kk + ((lane & 8) ? 8 : 0);
            #pragma unroll
            for (int nb=0; nb<2; nb++){
                unsigned tmp[4];
                ldm4(tmp, sptr(Bs + (brow + nb*16)*LDS + bcol));
                bf[2*nb][0]=tmp[0]; bf[2*nb][1]=tmp[1];
                bf[2*nb+1][0]=tmp[2]; bf[2*nb+1][1]=tmp[3];
                if (SPLIT){
                    ldm4(tmp, sptr(Bs2 + (brow + nb*16)*LDS + bcol));
                    bf2[2*nb][0]=tmp[0]; bf2[2*nb][1]=tmp[1];
                    bf2[2*nb+1][0]=tmp[2]; bf2[2*nb+1][1]=tmp[3];
                }
            }
            #pragma unroll
            for (int mi=0; mi<4; mi++)
                #pragma unroll
                for (int ni=0; ni<4; ni++){
                    mma16816(acc[mi][ni], af[mi], bf[ni]);
                    if (SPLIT){
                        mma16816(acc[mi][ni], af[mi],  bf2[ni]);
                        mma16816(acc[mi][ni], af2[mi], bf[ni]);
                    }
                }
        }
        __syncthreads();
    }

    // ---------------- epilogue ----------------
    int tr = lane >> 2, tc = (lane & 3) * 2;
    if (EPI == 2){
        __half* C = (__half*)Cout + z*batchC;
        const float inv = 1.0f/512.0f;
        float csum[4][2];
        #pragma unroll
        for (int ni=0; ni<4; ni++){ csum[ni][0]=0.f; csum[ni][1]=0.f; }
        #pragma unroll
        for (int mi=0; mi<4; mi++){
            #pragma unroll
            for (int ni=0; ni<4; ni++){
                int row = bm0 + wm*64 + mi*16 + tr;
                int col = bn0 + wn*32 + ni*8 + tc;
                float* a = acc[mi][ni];
                // round to fp16 FIRST, then sum the rounded value -> colsum and
                // rowsum see identical quantization (error cancels in the ratio)
                __half h0 = __float2half_rn(__expf(a[0]*inv));
                __half h1 = __float2half_rn(__expf(a[1]*inv));
                __half h2 = __float2half_rn(__expf(a[2]*inv));
                __half h3 = __float2half_rn(__expf(a[3]*inv));
                *(__half2*)(C + (long)row*ldc + col)     = __halves2half2(h0, h1);
                *(__half2*)(C + (long)(row+8)*ldc + col) = __halves2half2(h2, h3);
                csum[ni][0] += __half2float(h0) + __half2float(h2);
                csum[ni][1] += __half2float(h1) + __half2float(h3);
            }
        }
        #pragma unroll
        for (int ni=0; ni<4; ni++)
            #pragma unroll
            for (int j=0; j<2; j++){
                float s = csum[ni][j];
                s += __shfl_xor_sync(0xffffffffu, s, 4);
                s += __shfl_xor_sync(0xffffffffu, s, 8);
                s += __shfl_xor_sync(0xffffffffu, s, 16);
                csum[ni][j] = s;
            }
        float* cps = (float*)sm;   // smem reuse: all compute done (sync at loop end)
        if (lane < 4){
            #pragma unroll
            for (int ni=0; ni<4; ni++){
                cps[wm*128 + wn*32 + ni*8 + tc]     = csum[ni][0];
                cps[wm*128 + wn*32 + ni*8 + tc + 1] = csum[ni][1];
            }
        }
        __syncthreads();
        if (tid < 128)
            g_cpart[((long)z*32 + blockIdx.y)*SS + bn0 + tid] = cps[tid] + cps[128 + tid];
        return;
    }
    #pragma unroll
    for (int mi=0; mi<4; mi++){
        #pragma unroll
        for (int ni=0; ni<4; ni++){
            int row = bm0 + wm*64 + mi*16 + tr;
            int col = bn0 + wn*32 + ni*8 + tc;
            float* a = acc[mi][ni];
            if (EPI == 0){
                __nv_bfloat16* C = (__nv_bfloat16*)Cout;
                float b0 = bias[col], b1 = bias[col+1];
                *(__nv_bfloat162*)(C + (long)row*ldc + col)     = __floats2bfloat162_rn(a[0]+b0, a[1]+b1);
                *(__nv_bfloat162*)(C + (long)(row+8)*ldc + col) = __floats2bfloat162_rn(a[2]+b0, a[3]+b1);
            } else {  // EPI == 4: out = tanh(rs*(acc + c) + bl)
                float* C = (float*)Cout;
                float b0 = bias[col], b1 = bias[col+1];
                float c0 = cG[col],  c1 = cG[col+1];
                float r0 = rsG[row], r8 = rsG[row+8];
                *(float2*)(C + (long)row*ldc + col) =
                    make_float2(tanhf(r0*(a[0]+c0)+b0), tanhf(r0*(a[1]+c1)+b1));
                *(float2*)(C + (long)(row+8)*ldc + col) =
                    make_float2(tanhf(r8*(a[2]+c0)+b0), tanhf(r8*(a[3]+c1)+b1));
            }
        }
    }
}

// ---------------- rc[b,e] = 1 / sum of column partials ------------------------
__global__ void __launch_bounds__(256) rc_kernel(){
    int i = blockIdx.x*256 + threadIdx.x;       // 0..16383
    int b = i >> 12, e = i & (SS-1);
    const float* p = g_cpart + (long)b*32*SS + e;
    float s = 0.f;
    #pragma unroll
    for (int t = 0; t < 32; t++) s += p[(long)t*SS];
    g_rc[i] = 1.0f/s;
}

// ---------------- rowsum: rs[b,s] = sum_e E[b,s,e] * rc[b,e] ------------------
__global__ void __launch_bounds__(256) rowsum_kernel(){
    __shared__ float rcs[SS];
    int b = blockIdx.y;
    for (int i = threadIdx.x; i < SS; i += 256) rcs[i] = g_rc[b*SS + i];
    __syncthreads();
    int lane = threadIdx.x & 31, warp = threadIdx.x >> 5;
    int r0 = blockIdx.x*64 + warp*8;
    for (int k = 0; k < 8; k++){
        int r = r0 + k;
        const __half2* row = (const __half2*)(g_E + ((long)b*SS + r)*(long)SS);
        float s = 0.f;
        for (int j = lane; j < SS/2; j += 32){
            float2 f = __half22float2(row[j]);
            s += f.x*rcs[2*j] + f.y*rcs[2*j+1];
        }
        #pragma unroll
        for (int o = 16; o; o >>= 1) s += __shfl_xor_sync(0xffffffffu, s, o);
        if (lane == 0) g_rs[b*SS + r] = s;
    }
}

// ---------------- launch -----------------------------------------------------
extern "C" void kernel_launch(void* const* d_in, const int* in_sizes, int n_in,
                              void* d_out, int out_size)
{
    const float* xs = (const float*)d_in[0];
    const float* Wk = (const float*)d_in[1]; const float* bk = (const float*)d_in[2];
    const float* Wq = (const float*)d_in[3]; const float* bq = (const float*)d_in[4];
    const float* Wv = (const float*)d_in[5]; const float* bv = (const float*)d_in[6];
    const float* Wl = (const float*)d_in[7]; const float* bl = (const float*)d_in[8];

    void *p_xhi,*p_xlo,*p_KQ,*p_E,*p_bkq,*p_Wkq;
    void *p_Mhi,*p_Mlo,*p_rs,*p_c;
    cudaGetSymbolAddress(&p_xhi, g_xhi);   cudaGetSymbolAddress(&p_xlo, g_xlo);
    cudaGetSymbolAddress(&p_KQ,  g_KQ);    cudaGetSymbolAddress(&p_E,   g_E);
    cudaGetSymbolAddress(&p_bkq, g_bkq);   cudaGetSymbolAddress(&p_Wkq, g_Wkq);
    cudaGetSymbolAddress(&p_Mhi, g_Mhi);   cudaGetSymbolAddress(&p_Mlo, g_Mlo);
    cudaGetSymbolAddress(&p_rs,  g_rs);    cudaGetSymbolAddress(&p_c,   g_c);

    constexpr int AR = Bb_M*LDS;
    const size_t smemPlain = (size_t)2*AR*sizeof(__nv_bfloat16);   // 20480
    const size_t smemSplit = (size_t)4*AR*sizeof(__nv_bfloat16);   // 40960

    // 1. prep (x split, K|Q weight stack) + M = Wl@Wv split + c = Wl@bv
    prep_kernel<<<(BSD + 255)/256, 256>>>(xs, Wk, Wq, bk, bq);
    matM_kernel<<<dim3(DD/16, DD/16), dim3(16,16)>>>(Wl, Wv);
    cvec_kernel<<<DD/8, 256>>>(Wl, bv);

    // 2. merged K|Q projection -> g_KQ [16384, 1024]
    dim3 gkq(2*DD/Bb_N, (BB*SS)/Bb_M, 1);   // (8, 128)
    gemm_kernel<0,false><<<gkq, 256, smemPlain>>>(
        (const __nv_bfloat16*)p_xhi, nullptr, (const __nv_bfloat16*)p_Wkq, nullptr,
        (const float*)p_bkq, p_KQ, DD, DD, DD, 2*DD, 0, 0, 0, nullptr, nullptr);

    // 3. E = exp(K Q^T / 512) fp16 + fused fp16-rounded column partials
    dim3 gq(SS/Bb_N, SS/Bb_M, BB);          // (32, 32, 4)
    gemm_kernel<2,false><<<gq, 256, smemPlain>>>(
        (const __nv_bfloat16*)p_KQ, nullptr,
        (const __nv_bfloat16*)p_KQ + DD, nullptr,
        nullptr, p_E, DD, 2*DD, 2*DD, SS,
        (long)SS*2*DD, (long)SS*2*DD, (long)SS*SS, nullptr, nullptr);

    // 4. rc = 1/colsum; 5. rowsum
    rc_kernel<<<BB*SS/256, 256>>>();
    rowsum_kernel<<<dim3(SS/64, BB), 256>>>();

    // 6. out = tanh(rs*(x M^T + c) + bl)  — single fused split GEMM
    dim3 gp(DD/Bb_N, (BB*SS)/Bb_M, 1);      // (4, 128)
    gemm_kernel<4,true><<<gp, 256, smemSplit>>>(
        (const __nv_bfloat16*)p_xhi, (const __nv_bfloat16*)p_xlo,
        (const __nv_bfloat16*)p_Mhi, (const __nv_bfloat16*)p_Mlo,
        bl, d_out, DD, DD, DD, DD, 0, 0, 0,
        (const float*)p_rs, (const float*)p_c);
}